// round 3
// baseline (speedup 1.0000x reference)
#include <cuda_runtime.h>
#include <math.h>

// Problem constants
constexpr int Bc = 8;
constexpr int Cc = 64;
constexpr int Nc = 4096;
constexpr int Kc = 20;
constexpr int Oc = 64;
constexpr float BN_EPS = 1e-5f;
constexpr float NEG_SLOPE = 0.2f;
constexpr float FLT_BIG = 3.4e38f;

constexpr int SPLIT = 4;          // j-dimension splits for the KNN kernel
constexpr int JR = Nc / SPLIT;    // 1024 candidates per split
constexpr int TJ2 = 32;           // j tile per iteration
constexpr int QPT = 2;            // queries per thread

// -------------------- device scratch (no allocations allowed) --------------------
__device__ float  g_xx[Bc * Nc];                  // squared norms
__device__ int    g_idx[Bc * Nc * Kc];            // final knn indices
__device__ float  g_pd[Bc * SPLIT * Nc * Kc];     // partial top-k dists
__device__ int    g_pi[Bc * SPLIT * Nc * Kc];     // partial top-k indices
__device__ float  g_P[Bc * Nc * Oc];              // W1 . x_j   projection
__device__ float  g_Q[Bc * Nc * Oc];              // (W2-W1) . x_i projection
__device__ float  g_mx[Bc * Nc * Oc];             // max_k h
__device__ float  g_mn[Bc * Nc * Oc];             // min_k h
__device__ double g_sum[Oc];
__device__ double g_sumsq[Oc];
__device__ float  g_scale[Oc];
__device__ float  g_shift[Oc];
__device__ float  g_W1t[Cc * Oc];                 // W[:, :C] transposed [c][o]
__device__ float  g_Wdt[Cc * Oc];                 // W[:, C:] - W[:, :C] transposed [c][o]

// -------------------- f32x2 packed helpers (sm_103a FFMA2 path) --------------------
__device__ __forceinline__ unsigned long long pack2(float lo, float hi) {
    unsigned long long r;
    asm("mov.b64 %0, {%1, %2};" : "=l"(r) : "f"(lo), "f"(hi));
    return r;
}
__device__ __forceinline__ void unpack2(unsigned long long v, float& lo, float& hi) {
    asm("mov.b64 {%0, %1}, %2;" : "=f"(lo), "=f"(hi) : "l"(v));
}
__device__ __forceinline__ void ffma2(unsigned long long& d,
                                      unsigned long long a, unsigned long long b) {
    asm("fma.rn.f32x2 %0, %1, %2, %0;" : "+l"(d) : "l"(a), "l"(b));
}

// -------------------- kernel: squared norms --------------------
__global__ void k_xx(const float* __restrict__ x) {
    int t = blockIdx.x * blockDim.x + threadIdx.x;    // over B*N
    int b = t >> 12;
    int n = t & (Nc - 1);
    const float* xb = x + (size_t)b * Cc * Nc + n;
    float s = 0.f;
#pragma unroll
    for (int c = 0; c < Cc; ++c) {
        float v = xb[c * Nc];
        s = fmaf(v, v, s);
    }
    g_xx[t] = s;
}

// -------------------- kernel: prep W transposes + zero stats --------------------
__global__ void k_prep(const float* __restrict__ W) {
    int t = blockIdx.x * blockDim.x + threadIdx.x;
    if (t < Cc * Oc) {
        int c = t & 63;
        int o = t >> 6;
        float w1 = W[o * (2 * Cc) + c];
        float w2 = W[o * (2 * Cc) + Cc + c];
        g_W1t[c * Oc + o] = w1;
        g_Wdt[c * Oc + o] = w2 - w1;
    }
    if (blockIdx.x == 0 && t < Oc) {
        g_sum[t] = 0.0;
        g_sumsq[t] = 0.0;
    }
}

// -------------------- kernel: P and Q projections --------------------
__global__ void __launch_bounds__(256) k_pq(const float* __restrict__ x) {
    int b  = blockIdx.y;
    int n0 = blockIdx.x * 32;
    int o  = threadIdx.x & 63;
    int gg = threadIdx.x >> 6;
    __shared__ float xs[Cc][36];

    for (int t = threadIdx.x; t < Cc * 32; t += 256) {
        int nn = t & 31;
        int c  = t >> 5;
        xs[c][nn] = x[(size_t)b * Cc * Nc + c * Nc + n0 + nn];
    }
    __syncthreads();

    float ap[8], aq[8];
#pragma unroll
    for (int r = 0; r < 8; ++r) { ap[r] = 0.f; aq[r] = 0.f; }
    const int nbase = gg * 8;

#pragma unroll 8
    for (int c = 0; c < Cc; ++c) {
        float w1 = __ldg(&g_W1t[c * Oc + o]);
        float wd = __ldg(&g_Wdt[c * Oc + o]);
        float4 v0 = *(const float4*)&xs[c][nbase];
        float4 v1 = *(const float4*)&xs[c][nbase + 4];
        ap[0] = fmaf(w1, v0.x, ap[0]); aq[0] = fmaf(wd, v0.x, aq[0]);
        ap[1] = fmaf(w1, v0.y, ap[1]); aq[1] = fmaf(wd, v0.y, aq[1]);
        ap[2] = fmaf(w1, v0.z, ap[2]); aq[2] = fmaf(wd, v0.z, aq[2]);
        ap[3] = fmaf(w1, v0.w, ap[3]); aq[3] = fmaf(wd, v0.w, aq[3]);
        ap[4] = fmaf(w1, v1.x, ap[4]); aq[4] = fmaf(wd, v1.x, aq[4]);
        ap[5] = fmaf(w1, v1.y, ap[5]); aq[5] = fmaf(wd, v1.y, aq[5]);
        ap[6] = fmaf(w1, v1.z, ap[6]); aq[6] = fmaf(wd, v1.z, aq[6]);
        ap[7] = fmaf(w1, v1.w, ap[7]); aq[7] = fmaf(wd, v1.w, aq[7]);
    }

    int row0 = b * Nc + n0 + nbase;
#pragma unroll
    for (int r = 0; r < 8; ++r) {
        g_P[(size_t)(row0 + r) * Oc + o] = ap[r];
        g_Q[(size_t)(row0 + r) * Oc + o] = aq[r];
    }
}

// -------------------- kernel: KNN, 2 queries/thread, f32x2 math, shared top-k ----
// grid = (N/128, B, SPLIT), block = 64. Thread t owns queries i0 = bx*128+t and
// i1 = i0+64; each j-tile LDS feeds both queries (4 FFMA2 per LDS.128).
__global__ void __launch_bounds__(64) k_knn2(const float* __restrict__ x) {
    int b   = blockIdx.y;
    int s   = blockIdx.z;
    int tid = threadIdx.x;
    int i0  = blockIdx.x * (64 * QPT) + tid;
    int i1  = i0 + 64;
    const float* xb = x + (size_t)b * Cc * Nc;

    // both query vectors packed f32x2, pre-scaled by -2 (folds -2*inner)
    unsigned long long qa[32], qb[32];
#pragma unroll
    for (int cp = 0; cp < 32; ++cp) {
        const float* r0 = xb + (2 * cp) * Nc;
        const float* r1 = xb + (2 * cp + 1) * Nc;
        qa[cp] = pack2(r0[i0] * -2.f, r1[i0] * -2.f);
        qb[cp] = pack2(r0[i1] * -2.f, r1[i1] * -2.f);
    }
    float xxa = g_xx[b * Nc + i0];
    float xxb = g_xx[b * Nc + i1];

    __shared__ unsigned long long s2[TJ2][34];  // point tile, packed channel pairs
    __shared__ float sxx[TJ2];
    __shared__ float sd[Kc][128];               // per-query top-k dists
    __shared__ int   si[Kc][128];               // per-query top-k indices
#pragma unroll
    for (int kk = 0; kk < Kc; ++kk) {
        sd[kk][tid] = FLT_BIG;       si[kk][tid] = -1;
        sd[kk][tid + 64] = FLT_BIG;  si[kk][tid + 64] = -1;
    }
    float worsta = FLT_BIG, worstb = FLT_BIG;

    const int j0beg = s * JR;
    for (int j0 = j0beg; j0 < j0beg + JR; j0 += TJ2) {
        __syncthreads();
#pragma unroll
        for (int t = tid; t < TJ2 * 32; t += 64) {
            int jj = t & (TJ2 - 1);
            int cp = t >> 5;
            float a  = xb[(2 * cp) * Nc + j0 + jj];
            float c2 = xb[(2 * cp + 1) * Nc + j0 + jj];
            s2[jj][cp] = pack2(a, c2);
        }
        if (tid < TJ2) sxx[tid] = g_xx[b * Nc + j0 + tid];
        __syncthreads();

#pragma unroll 1
        for (int jj = 0; jj < TJ2; jj += 4) {
            unsigned long long aca[4], acb[4];
#pragma unroll
            for (int r = 0; r < 4; ++r) { aca[r] = 0ULL; acb[r] = 0ULL; }

#pragma unroll
            for (int cp = 0; cp < 32; cp += 2) {
#pragma unroll
                for (int r = 0; r < 4; ++r) {
                    ulonglong2 v = *(const ulonglong2*)&s2[jj + r][cp];
                    ffma2(aca[r], qa[cp], v.x);
                    ffma2(aca[r], qa[cp + 1], v.y);
                    ffma2(acb[r], qb[cp], v.x);
                    ffma2(acb[r], qb[cp + 1], v.y);
                }
            }

#pragma unroll
            for (int r = 0; r < 4; ++r) {
                float lo, hi;
                int jidx = j0 + jj + r;
                float sx = sxx[jj + r];
                unpack2(aca[r], lo, hi);
                float da = xxa + sx + (lo + hi);
                if (da < worsta) {
                    int p = Kc - 1;
                    while (p > 0) {
                        float v = sd[p - 1][tid];
                        if (!(v > da)) break;
                        sd[p][tid] = v;
                        si[p][tid] = si[p - 1][tid];
                        --p;
                    }
                    sd[p][tid] = da;
                    si[p][tid] = jidx;
                    worsta = sd[Kc - 1][tid];
                }
                unpack2(acb[r], lo, hi);
                float db = xxb + sx + (lo + hi);
                if (db < worstb) {
                    int p = Kc - 1;
                    while (p > 0) {
                        float v = sd[p - 1][tid + 64];
                        if (!(v > db)) break;
                        sd[p][tid + 64] = v;
                        si[p][tid + 64] = si[p - 1][tid + 64];
                        --p;
                    }
                    sd[p][tid + 64] = db;
                    si[p][tid + 64] = jidx;
                    worstb = sd[Kc - 1][tid + 64];
                }
            }
        }
    }

    size_t base0 = (((size_t)b * SPLIT + s) * Nc + i0) * Kc;
    size_t base1 = (((size_t)b * SPLIT + s) * Nc + i1) * Kc;
#pragma unroll
    for (int kk = 0; kk < Kc; ++kk) {
        g_pd[base0 + kk] = sd[kk][tid];
        g_pi[base0 + kk] = si[kk][tid];
        g_pd[base1 + kk] = sd[kk][tid + 64];
        g_pi[base1 + kk] = si[kk][tid + 64];
    }
}

// -------------------- kernel: merge SPLIT sorted partial top-k lists --------------------
__global__ void __launch_bounds__(256) k_merge() {
    int t = blockIdx.x * blockDim.x + threadIdx.x;   // over B*N
    int b = t >> 12;
    int i = t & (Nc - 1);
    float td[Kc];
    int   ti[Kc];
#pragma unroll
    for (int kk = 0; kk < Kc; ++kk) { td[kk] = FLT_BIG; ti[kk] = -1; }
    float worst = FLT_BIG;

    for (int s = 0; s < SPLIT; ++s) {
        size_t base = (((size_t)b * SPLIT + s) * Nc + i) * Kc;
#pragma unroll 1
        for (int kk = 0; kk < Kc; ++kk) {
            float d = g_pd[base + kk];
            if (!(d < worst)) break;   // lists sorted ascending; rest can't qualify
            int j = g_pi[base + kk];
            int p = Kc - 1;
            while (p > 0 && td[p - 1] > d) {
                td[p] = td[p - 1];
                ti[p] = ti[p - 1];
                --p;
            }
            td[p] = d;
            ti[p] = j;
            worst = td[Kc - 1];
        }
    }

    int* op = &g_idx[(size_t)t * Kc];
#pragma unroll
    for (int kk = 0; kk < Kc; ++kk) op[kk] = ti[kk];
}

// -------------------- kernel: gather + max/min + BN stats --------------------
__global__ void __launch_bounds__(256) k_edge() {
    int o  = threadIdx.x & 63;
    int gg = threadIdx.x >> 6;
    float s1 = 0.f, s2v = 0.f;

    for (int row = blockIdx.x * 4 + gg; row < Bc * Nc; row += gridDim.x * 4) {
        int b  = row >> 12;
        int nb = b << 12;
        float qv = g_Q[(size_t)row * Oc + o];
        const int* ip = &g_idx[(size_t)row * Kc];
        float mx = -FLT_BIG, mn = FLT_BIG;
#pragma unroll
        for (int kk = 0; kk < Kc; ++kk) {
            int j = __ldg(&ip[kk]);
            float h = g_P[(size_t)(nb + j) * Oc + o] + qv;
            mx = fmaxf(mx, h);
            mn = fminf(mn, h);
            s1 += h;
            s2v = fmaf(h, h, s2v);
        }
        g_mx[(size_t)row * Oc + o] = mx;
        g_mn[(size_t)row * Oc + o] = mn;
    }

    __shared__ float sa[4][64], sb[4][64];
    sa[gg][o] = s1;
    sb[gg][o] = s2v;
    __syncthreads();
    if (gg == 0) {
        float t1 = sa[0][o] + sa[1][o] + sa[2][o] + sa[3][o];
        float t2 = sb[0][o] + sb[1][o] + sb[2][o] + sb[3][o];
        atomicAdd(&g_sum[o], (double)t1);
        atomicAdd(&g_sumsq[o], (double)t2);
    }
}

// -------------------- kernel: finalize BN affine --------------------
__global__ void k_fin(const float* __restrict__ gamma, const float* __restrict__ beta) {
    int o = threadIdx.x;
    const double cnt = (double)Bc * Nc * Kc;
    double mean = g_sum[o] / cnt;
    double var  = g_sumsq[o] / cnt - mean * mean;
    float a = gamma[o] * rsqrtf((float)var + BN_EPS);
    g_scale[o] = a;
    g_shift[o] = beta[o] - (float)mean * a;
}

// -------------------- kernel: apply affine + leaky + transpose to [B,O,N] --------------------
__global__ void __launch_bounds__(256) k_out(float* __restrict__ out) {
    int b  = blockIdx.y;
    int n0 = blockIdx.x * 64;
    __shared__ float sh[64][65];

    for (int t = threadIdx.x; t < 4096; t += 256) {
        int o  = t & 63;
        int nn = t >> 6;
        int row = b * Nc + n0 + nn;
        float a = g_scale[o];
        float m = (a >= 0.f) ? g_mx[(size_t)row * Oc + o] : g_mn[(size_t)row * Oc + o];
        float v = fmaf(a, m, g_shift[o]);
        v = (v >= 0.f) ? v : NEG_SLOPE * v;
        sh[o][nn] = v;
    }
    __syncthreads();
    for (int t = threadIdx.x; t < 4096; t += 256) {
        int nn = t & 63;
        int o  = t >> 6;
        out[((size_t)(b * Oc + o)) * Nc + n0 + nn] = sh[o][nn];
    }
}

// -------------------- launch --------------------
extern "C" void kernel_launch(void* const* d_in, const int* in_sizes, int n_in,
                              void* d_out, int out_size) {
    const float* x     = (const float*)d_in[0];   // [B, C, N]
    const float* W     = (const float*)d_in[1];   // [O, 2C]
    const float* gamma = (const float*)d_in[2];   // [O]
    const float* beta  = (const float*)d_in[3];   // [O]
    float* out = (float*)d_out;                   // [B, O, N]

    k_xx<<<(Bc * Nc) / 256, 256>>>(x);
    k_prep<<<16, 256>>>(W);
    k_pq<<<dim3(Nc / 32, Bc), 256>>>(x);
    k_knn2<<<dim3(Nc / (64 * QPT), Bc, SPLIT), 64>>>(x);
    k_merge<<<(Bc * Nc) / 256, 256>>>();
    k_edge<<<512, 256>>>();
    k_fin<<<1, Oc>>>(gamma, beta);
    k_out<<<dim3(Nc / 64, Bc), 256>>>(out);
}

// round 4
// speedup vs baseline: 1.0651x; 1.0651x over previous
#include <cuda_runtime.h>
#include <math.h>

// Problem constants
constexpr int Bc = 8;
constexpr int Cc = 64;
constexpr int Nc = 4096;
constexpr int Kc = 20;
constexpr int Oc = 64;
constexpr float BN_EPS = 1e-5f;
constexpr float NEG_SLOPE = 0.2f;
constexpr float FLT_BIG = 3.4e38f;

constexpr int TI = 64;    // queries per block
constexpr int TJ = 64;    // candidate tile size
constexpr int PAD = 68;   // padded row stride in floats (272B, 16B-aligned)

// -------------------- device scratch (no allocations allowed) --------------------
__device__ float  g_xx[Bc * Nc];            // squared norms
__device__ int    g_idx[Bc * Nc * Kc];      // knn indices
__device__ float  g_P[Bc * Nc * Oc];        // W1 . x_j projection
__device__ float  g_Q[Bc * Nc * Oc];        // (W2-W1) . x_i projection
__device__ float  g_mx[Bc * Nc * Oc];       // max_k h
__device__ float  g_mn[Bc * Nc * Oc];       // min_k h
__device__ double g_sum[Oc];
__device__ double g_sumsq[Oc];
__device__ float  g_scale[Oc];
__device__ float  g_shift[Oc];
__device__ float  g_W1t[Cc * Oc];
__device__ float  g_Wdt[Cc * Oc];

// -------------------- kernel: squared norms --------------------
__global__ void k_xx(const float* __restrict__ x) {
    int t = blockIdx.x * blockDim.x + threadIdx.x;    // over B*N
    int b = t >> 12;
    int n = t & (Nc - 1);
    const float* xb = x + (size_t)b * Cc * Nc + n;
    float s = 0.f;
#pragma unroll
    for (int c = 0; c < Cc; ++c) {
        float v = xb[c * Nc];
        s = fmaf(v, v, s);
    }
    g_xx[t] = s;
}

// -------------------- kernel: prep W transposes + zero stats --------------------
__global__ void k_prep(const float* __restrict__ W) {
    int t = blockIdx.x * blockDim.x + threadIdx.x;
    if (t < Cc * Oc) {
        int c = t & 63;
        int o = t >> 6;
        float w1 = W[o * (2 * Cc) + c];
        float w2 = W[o * (2 * Cc) + Cc + c];
        g_W1t[c * Oc + o] = w1;
        g_Wdt[c * Oc + o] = w2 - w1;
    }
    if (blockIdx.x == 0 && t < Oc) {
        g_sum[t] = 0.0;
        g_sumsq[t] = 0.0;
    }
}

// -------------------- kernel: P and Q projections --------------------
__global__ void __launch_bounds__(256) k_pq(const float* __restrict__ x) {
    int b  = blockIdx.y;
    int n0 = blockIdx.x * 32;
    int o  = threadIdx.x & 63;
    int gg = threadIdx.x >> 6;
    __shared__ float xs[Cc][36];

    for (int t = threadIdx.x; t < Cc * 32; t += 256) {
        int nn = t & 31;
        int c  = t >> 5;
        xs[c][nn] = x[(size_t)b * Cc * Nc + c * Nc + n0 + nn];
    }
    __syncthreads();

    float ap[8], aq[8];
#pragma unroll
    for (int r = 0; r < 8; ++r) { ap[r] = 0.f; aq[r] = 0.f; }
    const int nbase = gg * 8;

#pragma unroll 8
    for (int c = 0; c < Cc; ++c) {
        float w1 = __ldg(&g_W1t[c * Oc + o]);
        float wd = __ldg(&g_Wdt[c * Oc + o]);
        float4 v0 = *(const float4*)&xs[c][nbase];
        float4 v1 = *(const float4*)&xs[c][nbase + 4];
        ap[0] = fmaf(w1, v0.x, ap[0]); aq[0] = fmaf(wd, v0.x, aq[0]);
        ap[1] = fmaf(w1, v0.y, ap[1]); aq[1] = fmaf(wd, v0.y, aq[1]);
        ap[2] = fmaf(w1, v0.z, ap[2]); aq[2] = fmaf(wd, v0.z, aq[2]);
        ap[3] = fmaf(w1, v0.w, ap[3]); aq[3] = fmaf(wd, v0.w, aq[3]);
        ap[4] = fmaf(w1, v1.x, ap[4]); aq[4] = fmaf(wd, v1.x, aq[4]);
        ap[5] = fmaf(w1, v1.y, ap[5]); aq[5] = fmaf(wd, v1.y, aq[5]);
        ap[6] = fmaf(w1, v1.z, ap[6]); aq[6] = fmaf(wd, v1.z, aq[6]);
        ap[7] = fmaf(w1, v1.w, ap[7]); aq[7] = fmaf(wd, v1.w, aq[7]);
    }

    int row0 = b * Nc + n0 + nbase;
#pragma unroll
    for (int r = 0; r < 8; ++r) {
        g_P[(size_t)(row0 + r) * Oc + o] = ap[r];
        g_Q[(size_t)(row0 + r) * Oc + o] = aq[r];
    }
}

// -------------------- kernel: GEMM-tiled KNN --------------------
// grid = (N/64, B), block = 256, dynamic smem.
// Per block: 64 queries. j loop over N in tiles of 64.
// Compute: thread (ti = tid&15, tj = tid>>4) owns a 4x4 (i,j) sub-tile.
// Distances go to shared Ds[j][i]; scan phase: thread (qi = tid&63, qq = tid>>6)
// scans j in [qq*16, qq*16+16) of the previous tile, keeping top-K in shared.
// Final: thread qi < 64 merges the 4 quarter lists (lex tie-break) -> g_idx.
__global__ void __launch_bounds__(256) k_knn3(const float* __restrict__ x) {
    extern __shared__ float sm[];
    float* As   = sm;                      // [64][PAD]  (row=c, col=i)
    float* Bs   = sm + 64 * PAD;           // [64][PAD]  (row=c, col=j)
    float* Ds   = sm + 2 * 64 * PAD;       // [64][PAD]  (row=j, col=i)
    float* sxxi = sm + 3 * 64 * PAD;       // [64]
    float* sxxj = sxxi + 64;               // [64]
    float* sd   = sxxj + 64;               // [Kc][256]
    int*   si   = (int*)(sd + Kc * 256);   // [Kc][256]

    const int tid = threadIdx.x;
    const int b   = blockIdx.y;
    const int i0  = blockIdx.x * TI;
    const float* xb = x + (size_t)b * Cc * Nc;

    // load A tile: As[c][ii] = x[b][c][i0+ii]  (float4 along i, coalesced)
    {
        int iq = tid & 15;
        int cg = tid >> 4;
#pragma unroll
        for (int cc = 0; cc < 4; ++cc) {
            int c = cc * 16 + cg;
            float4 v = *(const float4*)&xb[(size_t)c * Nc + i0 + iq * 4];
            *(float4*)&As[c * PAD + iq * 4] = v;
        }
    }
    if (tid < 64) sxxi[tid] = g_xx[b * Nc + i0 + tid];
#pragma unroll
    for (int kk = 0; kk < Kc; ++kk) {
        sd[kk * 256 + tid] = FLT_BIG;
        si[kk * 256 + tid] = 0x7fffffff;
    }

    const int ti = tid & 15;
    const int tj = tid >> 4;
    const int qi = tid & 63;
    const int qq = tid >> 6;
    float worst = FLT_BIG;

    __syncthreads();
    float xi4[4];
#pragma unroll
    for (int r = 0; r < 4; ++r) xi4[r] = sxxi[ti * 4 + r];

    for (int t = 0; t < Nc / TJ; ++t) {
        const int j0 = t * TJ;
        // load B tile (Bs free since previous compute ended at the bottom sync)
        {
            int jq = tid & 15;
            int cg = tid >> 4;
#pragma unroll
            for (int cc = 0; cc < 4; ++cc) {
                int c = cc * 16 + cg;
                float4 v = *(const float4*)&xb[(size_t)c * Nc + j0 + jq * 4];
                *(float4*)&Bs[c * PAD + jq * 4] = v;
            }
        }
        if (tid < 64) sxxj[tid] = g_xx[b * Nc + j0 + tid];

        // scan previous tile's distances (overlaps the B loads above)
        if (t > 0) {
            const int jp0 = j0 - TJ;
#pragma unroll 1
            for (int jj = 0; jj < 16; ++jj) {
                int jl = qq * 16 + jj;
                float d = Ds[jl * PAD + qi];
                if (d < worst) {
                    int jg = jp0 + jl;
                    int p = Kc - 1;
                    while (p > 0) {
                        float v = sd[(p - 1) * 256 + tid];
                        if (!(v > d)) break;
                        sd[p * 256 + tid] = v;
                        si[p * 256 + tid] = si[(p - 1) * 256 + tid];
                        --p;
                    }
                    sd[p * 256 + tid] = d;
                    si[p * 256 + tid] = jg;
                    worst = sd[(Kc - 1) * 256 + tid];
                }
            }
        }
        __syncthreads();   // B ready; Ds free for rewrite

        // compute 4x4 inner products over c
        float a00 = 0.f, a01 = 0.f, a02 = 0.f, a03 = 0.f;
        float a10 = 0.f, a11 = 0.f, a12 = 0.f, a13 = 0.f;
        float a20 = 0.f, a21 = 0.f, a22 = 0.f, a23 = 0.f;
        float a30 = 0.f, a31 = 0.f, a32 = 0.f, a33 = 0.f;
#pragma unroll 8
        for (int c = 0; c < Cc; ++c) {
            float4 av = *(const float4*)&As[c * PAD + ti * 4];
            float4 bv = *(const float4*)&Bs[c * PAD + tj * 4];
            a00 = fmaf(av.x, bv.x, a00); a01 = fmaf(av.x, bv.y, a01);
            a02 = fmaf(av.x, bv.z, a02); a03 = fmaf(av.x, bv.w, a03);
            a10 = fmaf(av.y, bv.x, a10); a11 = fmaf(av.y, bv.y, a11);
            a12 = fmaf(av.y, bv.z, a12); a13 = fmaf(av.y, bv.w, a13);
            a20 = fmaf(av.z, bv.x, a20); a21 = fmaf(av.z, bv.y, a21);
            a22 = fmaf(av.z, bv.z, a22); a23 = fmaf(av.z, bv.w, a23);
            a30 = fmaf(av.w, bv.x, a30); a31 = fmaf(av.w, bv.y, a31);
            a32 = fmaf(av.w, bv.z, a32); a33 = fmaf(av.w, bv.w, a33);
        }

        // epilogue: dist = xxi + xxj - 2*inner, store Ds[j][i] (STS.128 along i)
        {
            float xj0 = sxxj[tj * 4 + 0];
            float xj1 = sxxj[tj * 4 + 1];
            float xj2 = sxxj[tj * 4 + 2];
            float xj3 = sxxj[tj * 4 + 3];
            float4 d0, d1, d2, d3;
            d0.x = xi4[0] + xj0 - 2.f * a00; d0.y = xi4[1] + xj0 - 2.f * a10;
            d0.z = xi4[2] + xj0 - 2.f * a20; d0.w = xi4[3] + xj0 - 2.f * a30;
            d1.x = xi4[0] + xj1 - 2.f * a01; d1.y = xi4[1] + xj1 - 2.f * a11;
            d1.z = xi4[2] + xj1 - 2.f * a21; d1.w = xi4[3] + xj1 - 2.f * a31;
            d2.x = xi4[0] + xj2 - 2.f * a02; d2.y = xi4[1] + xj2 - 2.f * a12;
            d2.z = xi4[2] + xj2 - 2.f * a22; d2.w = xi4[3] + xj2 - 2.f * a32;
            d3.x = xi4[0] + xj3 - 2.f * a03; d3.y = xi4[1] + xj3 - 2.f * a13;
            d3.z = xi4[2] + xj3 - 2.f * a23; d3.w = xi4[3] + xj3 - 2.f * a33;
            *(float4*)&Ds[(tj * 4 + 0) * PAD + ti * 4] = d0;
            *(float4*)&Ds[(tj * 4 + 1) * PAD + ti * 4] = d1;
            *(float4*)&Ds[(tj * 4 + 2) * PAD + ti * 4] = d2;
            *(float4*)&Ds[(tj * 4 + 3) * PAD + ti * 4] = d3;
        }
        __syncthreads();   // Ds visible; Bs consumed
    }

    // scan last tile
    {
        const int jp0 = Nc - TJ;
#pragma unroll 1
        for (int jj = 0; jj < 16; ++jj) {
            int jl = qq * 16 + jj;
            float d = Ds[jl * PAD + qi];
            if (d < worst) {
                int jg = jp0 + jl;
                int p = Kc - 1;
                while (p > 0) {
                    float v = sd[(p - 1) * 256 + tid];
                    if (!(v > d)) break;
                    sd[p * 256 + tid] = v;
                    si[p * 256 + tid] = si[(p - 1) * 256 + tid];
                    --p;
                }
                sd[p * 256 + tid] = d;
                si[p * 256 + tid] = jg;
                worst = sd[(Kc - 1) * 256 + tid];
            }
        }
    }
    __syncthreads();

    // merge the 4 quarter lists per query (lexicographic tie-break = top_k order)
    if (tid < 64) {
        float td[Kc];
        int   tix[Kc];
#pragma unroll
        for (int kk = 0; kk < Kc; ++kk) { td[kk] = FLT_BIG; tix[kk] = 0x7fffffff; }
        for (int s = 0; s < 4; ++s) {
#pragma unroll 1
            for (int kk = 0; kk < Kc; ++kk) {
                float d = sd[kk * 256 + s * 64 + tid];
                int   j = si[kk * 256 + s * 64 + tid];
                float wd = td[Kc - 1];
                int   wj = tix[Kc - 1];
                if (d < wd || (d == wd && j < wj)) {
                    int p = Kc - 1;
                    while (p > 0 && (td[p - 1] > d || (td[p - 1] == d && tix[p - 1] > j))) {
                        td[p] = td[p - 1];
                        tix[p] = tix[p - 1];
                        --p;
                    }
                    td[p] = d;
                    tix[p] = j;
                } else if (!(d < wd)) {
                    break;  // list sorted ascending: nothing further qualifies
                }
            }
        }
        int* op = &g_idx[((size_t)(b * Nc + i0 + tid)) * Kc];
#pragma unroll
        for (int kk = 0; kk < Kc; ++kk) op[kk] = tix[kk];
    }
}

// -------------------- kernel: gather + max/min + BN stats --------------------
__global__ void __launch_bounds__(256) k_edge() {
    int o  = threadIdx.x & 63;
    int gg = threadIdx.x >> 6;
    float s1 = 0.f, s2v = 0.f;

    for (int row = blockIdx.x * 4 + gg; row < Bc * Nc; row += gridDim.x * 4) {
        int b  = row >> 12;
        int nb = b << 12;
        float qv = g_Q[(size_t)row * Oc + o];
        const int* ip = &g_idx[(size_t)row * Kc];
        float mx = -FLT_BIG, mn = FLT_BIG;
#pragma unroll
        for (int kk = 0; kk < Kc; ++kk) {
            int j = __ldg(&ip[kk]);
            float h = g_P[(size_t)(nb + j) * Oc + o] + qv;
            mx = fmaxf(mx, h);
            mn = fminf(mn, h);
            s1 += h;
            s2v = fmaf(h, h, s2v);
        }
        g_mx[(size_t)row * Oc + o] = mx;
        g_mn[(size_t)row * Oc + o] = mn;
    }

    __shared__ float sa[4][64], sb[4][64];
    sa[gg][o] = s1;
    sb[gg][o] = s2v;
    __syncthreads();
    if (gg == 0) {
        float t1 = sa[0][o] + sa[1][o] + sa[2][o] + sa[3][o];
        float t2 = sb[0][o] + sb[1][o] + sb[2][o] + sb[3][o];
        atomicAdd(&g_sum[o], (double)t1);
        atomicAdd(&g_sumsq[o], (double)t2);
    }
}

// -------------------- kernel: finalize BN affine --------------------
__global__ void k_fin(const float* __restrict__ gamma, const float* __restrict__ beta) {
    int o = threadIdx.x;
    const double cnt = (double)Bc * Nc * Kc;
    double mean = g_sum[o] / cnt;
    double var  = g_sumsq[o] / cnt - mean * mean;
    float a = gamma[o] * rsqrtf((float)var + BN_EPS);
    g_scale[o] = a;
    g_shift[o] = beta[o] - (float)mean * a;
}

// -------------------- kernel: apply affine + leaky + transpose to [B,O,N] --------------------
__global__ void __launch_bounds__(256) k_out(float* __restrict__ out) {
    int b  = blockIdx.y;
    int n0 = blockIdx.x * 64;
    __shared__ float sh[64][65];

    for (int t = threadIdx.x; t < 4096; t += 256) {
        int o  = t & 63;
        int nn = t >> 6;
        int row = b * Nc + n0 + nn;
        float a = g_scale[o];
        float m = (a >= 0.f) ? g_mx[(size_t)row * Oc + o] : g_mn[(size_t)row * Oc + o];
        float v = fmaf(a, m, g_shift[o]);
        v = (v >= 0.f) ? v : NEG_SLOPE * v;
        sh[o][nn] = v;
    }
    __syncthreads();
    for (int t = threadIdx.x; t < 4096; t += 256) {
        int nn = t & 63;
        int o  = t >> 6;
        out[((size_t)(b * Oc + o)) * Nc + n0 + nn] = sh[o][nn];
    }
}

// -------------------- launch --------------------
extern "C" void kernel_launch(void* const* d_in, const int* in_sizes, int n_in,
                              void* d_out, int out_size) {
    const float* x     = (const float*)d_in[0];   // [B, C, N]
    const float* W     = (const float*)d_in[1];   // [O, 2C]
    const float* gamma = (const float*)d_in[2];   // [O]
    const float* beta  = (const float*)d_in[3];   // [O]
    float* out = (float*)d_out;                   // [B, O, N]

    constexpr size_t KNN_SMEM =
        (size_t)(3 * 64 * PAD + 128 + Kc * 256) * 4 + (size_t)Kc * 256 * 4;

    static bool attr_set = false;
    if (!attr_set) {
        cudaFuncSetAttribute(k_knn3, cudaFuncAttributeMaxDynamicSharedMemorySize,
                             (int)KNN_SMEM);
        attr_set = true;
    }

    k_xx<<<(Bc * Nc) / 256, 256>>>(x);
    k_prep<<<16, 256>>>(W);
    k_pq<<<dim3(Nc / 32, Bc), 256>>>(x);
    k_knn3<<<dim3(Nc / TI, Bc), 256, KNN_SMEM>>>(x);
    k_edge<<<512, 256>>>();
    k_fin<<<1, Oc>>>(gamma, beta);
    k_out<<<dim3(Nc / 64, Bc), 256>>>(out);
}

// round 5
// speedup vs baseline: 1.4656x; 1.3761x over previous
#include <cuda_runtime.h>
#include <math.h>

// Problem constants
constexpr int Bc = 8;
constexpr int Cc = 64;
constexpr int Nc = 4096;
constexpr int Kc = 20;
constexpr int Oc = 64;
constexpr float BN_EPS = 1e-5f;
constexpr float NEG_SLOPE = 0.2f;
constexpr float FLT_BIG = 3.4e38f;

constexpr int TI = 128;    // queries per block
constexpr int TJ = 128;    // candidate tile size
constexpr int APAD = 132;  // padded row stride (floats), 16B-aligned

// -------------------- device scratch (no allocations allowed) --------------------
__device__ float  g_xx[Bc * Nc];            // squared norms
__device__ int    g_idx[Bc * Nc * Kc];      // knn indices
__device__ float  g_P[Bc * Nc * Oc];        // W1 . x_j projection
__device__ float  g_Q[Bc * Nc * Oc];        // (W2-W1) . x_i projection
__device__ float  g_mx[Bc * Nc * Oc];       // max_k h
__device__ float  g_mn[Bc * Nc * Oc];       // min_k h
__device__ double g_sum[Oc];
__device__ double g_sumsq[Oc];
__device__ float  g_scale[Oc];
__device__ float  g_shift[Oc];
__device__ float  g_W1t[Cc * Oc];
__device__ float  g_Wdt[Cc * Oc];

// -------------------- f32x2 packed helpers --------------------
typedef unsigned long long u64;
__device__ __forceinline__ u64 dup2(float v) {
    u64 r; asm("mov.b64 %0, {%1, %1};" : "=l"(r) : "f"(v)); return r;
}
__device__ __forceinline__ void ffma2(u64& d, u64 a, u64 b) {
    asm("fma.rn.f32x2 %0, %1, %2, %0;" : "+l"(d) : "l"(a), "l"(b));
}
__device__ __forceinline__ u64 fma2o(u64 a, u64 b, u64 c) {
    u64 r; asm("fma.rn.f32x2 %0, %1, %2, %3;" : "=l"(r) : "l"(a), "l"(b), "l"(c));
    return r;
}
__device__ __forceinline__ u64 add2(u64 a, u64 b) {
    u64 r; asm("add.rn.f32x2 %0, %1, %2;" : "=l"(r) : "l"(a), "l"(b));
    return r;
}

// -------------------- kernel: squared norms --------------------
__global__ void k_xx(const float* __restrict__ x) {
    int t = blockIdx.x * blockDim.x + threadIdx.x;    // over B*N
    int b = t >> 12;
    int n = t & (Nc - 1);
    const float* xb = x + (size_t)b * Cc * Nc + n;
    float s = 0.f;
#pragma unroll
    for (int c = 0; c < Cc; ++c) {
        float v = xb[c * Nc];
        s = fmaf(v, v, s);
    }
    g_xx[t] = s;
}

// -------------------- kernel: prep W transposes + zero stats --------------------
__global__ void k_prep(const float* __restrict__ W) {
    int t = blockIdx.x * blockDim.x + threadIdx.x;
    if (t < Cc * Oc) {
        int c = t & 63;
        int o = t >> 6;
        float w1 = W[o * (2 * Cc) + c];
        float w2 = W[o * (2 * Cc) + Cc + c];
        g_W1t[c * Oc + o] = w1;
        g_Wdt[c * Oc + o] = w2 - w1;
    }
    if (blockIdx.x == 0 && t < Oc) {
        g_sum[t] = 0.0;
        g_sumsq[t] = 0.0;
    }
}

// -------------------- kernel: P and Q projections --------------------
__global__ void __launch_bounds__(256) k_pq(const float* __restrict__ x) {
    int b  = blockIdx.y;
    int n0 = blockIdx.x * 32;
    int o  = threadIdx.x & 63;
    int gg = threadIdx.x >> 6;
    __shared__ float xs[Cc][36];

    for (int t = threadIdx.x; t < Cc * 32; t += 256) {
        int nn = t & 31;
        int c  = t >> 5;
        xs[c][nn] = x[(size_t)b * Cc * Nc + c * Nc + n0 + nn];
    }
    __syncthreads();

    float ap[8], aq[8];
#pragma unroll
    for (int r = 0; r < 8; ++r) { ap[r] = 0.f; aq[r] = 0.f; }
    const int nbase = gg * 8;

#pragma unroll 8
    for (int c = 0; c < Cc; ++c) {
        float w1 = __ldg(&g_W1t[c * Oc + o]);
        float wd = __ldg(&g_Wdt[c * Oc + o]);
        float4 v0 = *(const float4*)&xs[c][nbase];
        float4 v1 = *(const float4*)&xs[c][nbase + 4];
        ap[0] = fmaf(w1, v0.x, ap[0]); aq[0] = fmaf(wd, v0.x, aq[0]);
        ap[1] = fmaf(w1, v0.y, ap[1]); aq[1] = fmaf(wd, v0.y, aq[1]);
        ap[2] = fmaf(w1, v0.z, ap[2]); aq[2] = fmaf(wd, v0.z, aq[2]);
        ap[3] = fmaf(w1, v0.w, ap[3]); aq[3] = fmaf(wd, v0.w, aq[3]);
        ap[4] = fmaf(w1, v1.x, ap[4]); aq[4] = fmaf(wd, v1.x, aq[4]);
        ap[5] = fmaf(w1, v1.y, ap[5]); aq[5] = fmaf(wd, v1.y, aq[5]);
        ap[6] = fmaf(w1, v1.z, ap[6]); aq[6] = fmaf(wd, v1.z, aq[6]);
        ap[7] = fmaf(w1, v1.w, ap[7]); aq[7] = fmaf(wd, v1.w, aq[7]);
    }

    int row0 = b * Nc + n0 + nbase;
#pragma unroll
    for (int r = 0; r < 8; ++r) {
        g_P[(size_t)(row0 + r) * Oc + o] = ap[r];
        g_Q[(size_t)(row0 + r) * Oc + o] = aq[r];
    }
}

// -------------------- kernel: GEMM-tiled KNN, 8x8 register tile, f32x2 --------------------
// grid = (N/128, B), block = 256, dynamic smem.
// Thread (ti=tid&15, tj=tid>>4) owns an 8x8 (i,j) sub-tile; the 8 i's are held
// as 4 packed f32x2 pairs (natural layout in As), the 8 j values get duplicated
// into f32x2 broadcast operands. 32 FFMA2 per c-step per thread.
// Distances land in Ds[j][i]; scan phase: thread (qi=tid&127, qq=tid>>7) scans
// the j half-tile qq of the PREVIOUS tile (overlapped with B loads), keeping a
// per-(qi,qq) top-K list in shared; final lexicographic 2-way merge -> g_idx.
__global__ void __launch_bounds__(256) k_knn4(const float* __restrict__ x) {
    extern __shared__ float sm[];
    float* As   = sm;                        // [Cc][APAD] (row=c, col=i)
    float* Bs   = sm + Cc * APAD;            // [Cc][APAD] (row=c, col=j)
    float* Ds   = sm + 2 * Cc * APAD;        // [TJ][APAD] (row=j, col=i)
    float* sxxi = Ds + TJ * APAD;            // [128]
    float* sxxj = sxxi + 128;                // [128]
    float* sd   = sxxj + 128;                // [Kc][256]
    int*   si   = (int*)(sd + Kc * 256);     // [Kc][256]

    const int tid = threadIdx.x;
    const int b   = blockIdx.y;
    const int i0  = blockIdx.x * TI;
    const float* xb = x + (size_t)b * Cc * Nc;

    const int ti = tid & 15;
    const int tj = tid >> 4;
    const int qi = tid & 127;
    const int qq = tid >> 7;

    // load A tile: As[c][ii] = x[b][c][i0+ii]
    {
        int col = (tid & 31) * 4;
        int cb  = tid >> 5;
#pragma unroll
        for (int cc = 0; cc < 8; ++cc) {
            int c = cb + cc * 8;
            float4 v = *(const float4*)&xb[(size_t)c * Nc + i0 + col];
            *(float4*)&As[c * APAD + col] = v;
        }
    }
    if (tid < 128) sxxi[tid] = g_xx[b * Nc + i0 + tid];
#pragma unroll
    for (int kk = 0; kk < Kc; ++kk) {
        sd[kk * 256 + tid] = FLT_BIG;
        si[kk * 256 + tid] = 0x7fffffff;
    }
    __syncthreads();

    // packed query norms for this thread's 4 i-pairs
    u64 xq[4];
    {
        ulonglong2 t0 = *(const ulonglong2*)&sxxi[ti * 8];
        ulonglong2 t1 = *(const ulonglong2*)&sxxi[ti * 8 + 4];
        xq[0] = t0.x; xq[1] = t0.y; xq[2] = t1.x; xq[3] = t1.y;
    }
    const u64 neg2 = dup2(-2.f);
    float worst = FLT_BIG;

    for (int t = 0; t < Nc / TJ; ++t) {
        const int j0 = t * TJ;

        // load B tile global -> shared (overlaps with scan below)
        {
            int col = (tid & 31) * 4;
            int cb  = tid >> 5;
#pragma unroll
            for (int cc = 0; cc < 8; ++cc) {
                int c = cb + cc * 8;
                float4 v = *(const float4*)&xb[(size_t)c * Nc + j0 + col];
                *(float4*)&Bs[c * APAD + col] = v;
            }
        }
        if (tid < 128) sxxj[tid] = g_xx[b * Nc + j0 + tid];

        // scan previous tile's distances
        if (t > 0) {
            const int jp0 = j0 - TJ;
#pragma unroll 1
            for (int jj = 0; jj < 64; ++jj) {
                int jl = qq * 64 + jj;
                float d = Ds[jl * APAD + qi];
                if (d < worst) {
                    int jg = jp0 + jl;
                    int p = Kc - 1;
                    while (p > 0) {
                        float v = sd[(p - 1) * 256 + tid];
                        if (!(v > d)) break;
                        sd[p * 256 + tid] = v;
                        si[p * 256 + tid] = si[(p - 1) * 256 + tid];
                        --p;
                    }
                    sd[p * 256 + tid] = d;
                    si[p * 256 + tid] = jg;
                    worst = sd[(Kc - 1) * 256 + tid];
                }
            }
        }
        __syncthreads();   // B ready; Ds free for rewrite

        // ---- 8x8 f32x2 GEMM over c ----
        u64 acc[4][8];
#pragma unroll
        for (int ip = 0; ip < 4; ++ip)
#pragma unroll
            for (int j = 0; j < 8; ++j) acc[ip][j] = 0ULL;

#pragma unroll 4
        for (int c = 0; c < Cc; ++c) {
            ulonglong2 a01 = *(const ulonglong2*)&As[c * APAD + ti * 8];
            ulonglong2 a23 = *(const ulonglong2*)&As[c * APAD + ti * 8 + 4];
            u64 ap[4] = {a01.x, a01.y, a23.x, a23.y};
            float4 b0 = *(const float4*)&Bs[c * APAD + tj * 8];
            float4 b1 = *(const float4*)&Bs[c * APAD + tj * 8 + 4];
            u64 bd[8];
            bd[0] = dup2(b0.x); bd[1] = dup2(b0.y);
            bd[2] = dup2(b0.z); bd[3] = dup2(b0.w);
            bd[4] = dup2(b1.x); bd[5] = dup2(b1.y);
            bd[6] = dup2(b1.z); bd[7] = dup2(b1.w);
#pragma unroll
            for (int ip = 0; ip < 4; ++ip)
#pragma unroll
                for (int j = 0; j < 8; ++j)
                    ffma2(acc[ip][j], ap[ip], bd[j]);
        }

        // epilogue: d = xxi + xxj - 2*inner (packed), store Ds[j][i]
#pragma unroll
        for (int j = 0; j < 8; ++j) {
            u64 xjd = dup2(sxxj[tj * 8 + j]);
            int row = (tj * 8 + j) * APAD + ti * 8;
#pragma unroll
            for (int ip = 0; ip < 4; ++ip) {
                u64 pre = add2(xq[ip], xjd);
                u64 d2  = fma2o(acc[ip][j], neg2, pre);
                *(u64*)&Ds[row + ip * 2] = d2;
            }
        }
        __syncthreads();   // Ds visible; Bs consumed
    }

    // scan last tile
    {
        const int jp0 = Nc - TJ;
#pragma unroll 1
        for (int jj = 0; jj < 64; ++jj) {
            int jl = qq * 64 + jj;
            float d = Ds[jl * APAD + qi];
            if (d < worst) {
                int jg = jp0 + jl;
                int p = Kc - 1;
                while (p > 0) {
                    float v = sd[(p - 1) * 256 + tid];
                    if (!(v > d)) break;
                    sd[p * 256 + tid] = v;
                    si[p * 256 + tid] = si[(p - 1) * 256 + tid];
                    --p;
                }
                sd[p * 256 + tid] = d;
                si[p * 256 + tid] = jg;
                worst = sd[(Kc - 1) * 256 + tid];
            }
        }
    }
    __syncthreads();

    // merge the 2 half lists per query (lexicographic tie-break = top_k order)
    if (tid < 128) {
        float td[Kc];
        int   tix[Kc];
#pragma unroll
        for (int kk = 0; kk < Kc; ++kk) { td[kk] = FLT_BIG; tix[kk] = 0x7fffffff; }
        for (int s = 0; s < 2; ++s) {
#pragma unroll 1
            for (int kk = 0; kk < Kc; ++kk) {
                float d = sd[kk * 256 + s * 128 + tid];
                int   j = si[kk * 256 + s * 128 + tid];
                float wd = td[Kc - 1];
                int   wj = tix[Kc - 1];
                if (d < wd || (d == wd && j < wj)) {
                    int p = Kc - 1;
                    while (p > 0 && (td[p - 1] > d || (td[p - 1] == d && tix[p - 1] > j))) {
                        td[p] = td[p - 1];
                        tix[p] = tix[p - 1];
                        --p;
                    }
                    td[p] = d;
                    tix[p] = j;
                } else if (!(d < wd)) {
                    break;  // list sorted ascending: nothing further qualifies
                }
            }
        }
        int* op = &g_idx[((size_t)(b * Nc + i0 + tid)) * Kc];
#pragma unroll
        for (int kk = 0; kk < Kc; ++kk) op[kk] = tix[kk];
    }
}

// -------------------- kernel: gather + max/min + BN stats --------------------
__global__ void __launch_bounds__(256) k_edge() {
    int o  = threadIdx.x & 63;
    int gg = threadIdx.x >> 6;
    float s1 = 0.f, s2v = 0.f;

    for (int row = blockIdx.x * 4 + gg; row < Bc * Nc; row += gridDim.x * 4) {
        int b  = row >> 12;
        int nb = b << 12;
        float qv = g_Q[(size_t)row * Oc + o];
        const int* ip = &g_idx[(size_t)row * Kc];
        float mx = -FLT_BIG, mn = FLT_BIG;
#pragma unroll
        for (int kk = 0; kk < Kc; ++kk) {
            int j = __ldg(&ip[kk]);
            float h = g_P[(size_t)(nb + j) * Oc + o] + qv;
            mx = fmaxf(mx, h);
            mn = fminf(mn, h);
            s1 += h;
            s2v = fmaf(h, h, s2v);
        }
        g_mx[(size_t)row * Oc + o] = mx;
        g_mn[(size_t)row * Oc + o] = mn;
    }

    __shared__ float sa[4][64], sb[4][64];
    sa[gg][o] = s1;
    sb[gg][o] = s2v;
    __syncthreads();
    if (gg == 0) {
        float t1 = sa[0][o] + sa[1][o] + sa[2][o] + sa[3][o];
        float t2 = sb[0][o] + sb[1][o] + sb[2][o] + sb[3][o];
        atomicAdd(&g_sum[o], (double)t1);
        atomicAdd(&g_sumsq[o], (double)t2);
    }
}

// -------------------- kernel: finalize BN affine --------------------
__global__ void k_fin(const float* __restrict__ gamma, const float* __restrict__ beta) {
    int o = threadIdx.x;
    const double cnt = (double)Bc * Nc * Kc;
    double mean = g_sum[o] / cnt;
    double var  = g_sumsq[o] / cnt - mean * mean;
    float a = gamma[o] * rsqrtf((float)var + BN_EPS);
    g_scale[o] = a;
    g_shift[o] = beta[o] - (float)mean * a;
}

// -------------------- kernel: apply affine + leaky + transpose to [B,O,N] --------------------
__global__ void __launch_bounds__(256) k_out(float* __restrict__ out) {
    int b  = blockIdx.y;
    int n0 = blockIdx.x * 64;
    __shared__ float sh[64][65];

    for (int t = threadIdx.x; t < 4096; t += 256) {
        int o  = t & 63;
        int nn = t >> 6;
        int row = b * Nc + n0 + nn;
        float a = g_scale[o];
        float m = (a >= 0.f) ? g_mx[(size_t)row * Oc + o] : g_mn[(size_t)row * Oc + o];
        float v = fmaf(a, m, g_shift[o]);
        v = (v >= 0.f) ? v : NEG_SLOPE * v;
        sh[o][nn] = v;
    }
    __syncthreads();
    for (int t = threadIdx.x; t < 4096; t += 256) {
        int nn = t & 63;
        int o  = t >> 6;
        out[((size_t)(b * Oc + o)) * Nc + n0 + nn] = sh[o][nn];
    }
}

// -------------------- launch --------------------
extern "C" void kernel_launch(void* const* d_in, const int* in_sizes, int n_in,
                              void* d_out, int out_size) {
    const float* x     = (const float*)d_in[0];   // [B, C, N]
    const float* W     = (const float*)d_in[1];   // [O, 2C]
    const float* gamma = (const float*)d_in[2];   // [O]
    const float* beta  = (const float*)d_in[3];   // [O]
    float* out = (float*)d_out;                   // [B, O, N]

    constexpr size_t KNN_SMEM =
        (size_t)(2 * Cc * APAD + TJ * APAD + 256 + 2 * Kc * 256) * 4;

    static bool attr_set = false;
    if (!attr_set) {
        cudaFuncSetAttribute(k_knn4, cudaFuncAttributeMaxDynamicSharedMemorySize,
                             (int)KNN_SMEM);
        attr_set = true;
    }

    k_xx<<<(Bc * Nc) / 256, 256>>>(x);
    k_prep<<<16, 256>>>(W);
    k_pq<<<dim3(Nc / 32, Bc), 256>>>(x);
    k_knn4<<<dim3(Nc / TI, Bc), 256, KNN_SMEM>>>(x);
    k_edge<<<512, 256>>>();
    k_fin<<<1, Oc>>>(gamma, beta);
    k_out<<<dim3(Nc / 64, Bc), 256>>>(out);
}

// round 6
// speedup vs baseline: 1.6089x; 1.0978x over previous
#include <cuda_runtime.h>
#include <math.h>

// Problem constants
constexpr int Bc = 8;
constexpr int Cc = 64;
constexpr int Nc = 4096;
constexpr int Kc = 20;
constexpr int Oc = 64;
constexpr float BN_EPS = 1e-5f;
constexpr float NEG_SLOPE = 0.2f;
constexpr float FLT_BIG = 3.4e38f;

constexpr int TI = 128;      // queries per block
constexpr int TJ = 128;      // candidate tile size
constexpr int APAD = 132;    // padded row stride (floats)
constexpr int NT = 512;      // threads per block (knn)

// -------------------- device scratch (no allocations allowed) --------------------
__device__ float  g_xx[Bc * Nc];            // squared norms
__device__ int    g_idx[Bc * Nc * Kc];      // knn indices
__device__ float  g_P[Bc * Nc * Oc];        // W1 . x_j projection
__device__ float  g_Q[Bc * Nc * Oc];        // (W2-W1) . x_i projection
__device__ float  g_mx[Bc * Nc * Oc];       // max_k h
__device__ float  g_mn[Bc * Nc * Oc];       // min_k h
__device__ double g_sum[Oc];
__device__ double g_sumsq[Oc];
__device__ float  g_scale[Oc];
__device__ float  g_shift[Oc];
__device__ float  g_W1t[Cc * Oc];
__device__ float  g_Wdt[Cc * Oc];

// -------------------- f32x2 packed helpers --------------------
typedef unsigned long long u64;
typedef unsigned int u32;
__device__ __forceinline__ u64 dup2(float v) {
    u64 r; asm("mov.b64 %0, {%1, %1};" : "=l"(r) : "f"(v)); return r;
}
__device__ __forceinline__ void ffma2(u64& d, u64 a, u64 b) {
    asm("fma.rn.f32x2 %0, %1, %2, %0;" : "+l"(d) : "l"(a), "l"(b));
}
__device__ __forceinline__ u64 fma2o(u64 a, u64 b, u64 c) {
    u64 r; asm("fma.rn.f32x2 %0, %1, %2, %3;" : "=l"(r) : "l"(a), "l"(b), "l"(c));
    return r;
}
__device__ __forceinline__ u64 add2(u64 a, u64 b) {
    u64 r; asm("add.rn.f32x2 %0, %1, %2;" : "=l"(r) : "l"(a), "l"(b));
    return r;
}
// orderable float mapping: monotonic uint32 key (handles negatives)
__device__ __forceinline__ u32 ordf(float f) {
    u32 u = __float_as_uint(f);
    return (u & 0x80000000u) ? ~u : (u | 0x80000000u);
}

constexpr u64 KEY_MAX = 0xFFFFFFFFFFFFFFFFull;

// -------------------- kernel: squared norms --------------------
__global__ void k_xx(const float* __restrict__ x) {
    int t = blockIdx.x * blockDim.x + threadIdx.x;    // over B*N
    int b = t >> 12;
    int n = t & (Nc - 1);
    const float* xb = x + (size_t)b * Cc * Nc + n;
    float s = 0.f;
#pragma unroll
    for (int c = 0; c < Cc; ++c) {
        float v = xb[c * Nc];
        s = fmaf(v, v, s);
    }
    g_xx[t] = s;
}

// -------------------- kernel: prep W transposes + zero stats --------------------
__global__ void k_prep(const float* __restrict__ W) {
    int t = blockIdx.x * blockDim.x + threadIdx.x;
    if (t < Cc * Oc) {
        int c = t & 63;
        int o = t >> 6;
        float w1 = W[o * (2 * Cc) + c];
        float w2 = W[o * (2 * Cc) + Cc + c];
        g_W1t[c * Oc + o] = w1;
        g_Wdt[c * Oc + o] = w2 - w1;
    }
    if (blockIdx.x == 0 && t < Oc) {
        g_sum[t] = 0.0;
        g_sumsq[t] = 0.0;
    }
}

// -------------------- kernel: P and Q projections --------------------
__global__ void __launch_bounds__(256) k_pq(const float* __restrict__ x) {
    int b  = blockIdx.y;
    int n0 = blockIdx.x * 32;
    int o  = threadIdx.x & 63;
    int gg = threadIdx.x >> 6;
    __shared__ float xs[Cc][36];

    for (int t = threadIdx.x; t < Cc * 32; t += 256) {
        int nn = t & 31;
        int c  = t >> 5;
        xs[c][nn] = x[(size_t)b * Cc * Nc + c * Nc + n0 + nn];
    }
    __syncthreads();

    float ap[8], aq[8];
#pragma unroll
    for (int r = 0; r < 8; ++r) { ap[r] = 0.f; aq[r] = 0.f; }
    const int nbase = gg * 8;

#pragma unroll 8
    for (int c = 0; c < Cc; ++c) {
        float w1 = __ldg(&g_W1t[c * Oc + o]);
        float wd = __ldg(&g_Wdt[c * Oc + o]);
        float4 v0 = *(const float4*)&xs[c][nbase];
        float4 v1 = *(const float4*)&xs[c][nbase + 4];
        ap[0] = fmaf(w1, v0.x, ap[0]); aq[0] = fmaf(wd, v0.x, aq[0]);
        ap[1] = fmaf(w1, v0.y, ap[1]); aq[1] = fmaf(wd, v0.y, aq[1]);
        ap[2] = fmaf(w1, v0.z, ap[2]); aq[2] = fmaf(wd, v0.z, aq[2]);
        ap[3] = fmaf(w1, v0.w, ap[3]); aq[3] = fmaf(wd, v0.w, aq[3]);
        ap[4] = fmaf(w1, v1.x, ap[4]); aq[4] = fmaf(wd, v1.x, aq[4]);
        ap[5] = fmaf(w1, v1.y, ap[5]); aq[5] = fmaf(wd, v1.y, aq[5]);
        ap[6] = fmaf(w1, v1.z, ap[6]); aq[6] = fmaf(wd, v1.z, aq[6]);
        ap[7] = fmaf(w1, v1.w, ap[7]); aq[7] = fmaf(wd, v1.w, aq[7]);
    }

    int row0 = b * Nc + n0 + nbase;
#pragma unroll
    for (int r = 0; r < 8; ++r) {
        g_P[(size_t)(row0 + r) * Oc + o] = ap[r];
        g_Q[(size_t)(row0 + r) * Oc + o] = aq[r];
    }
}

// -------------------- kernel: GEMM-tiled KNN, 512 threads, 4x8 f32x2 tile --------------------
// grid = (N/128, B), block = 512, dynamic smem (~213 KB).
// Compute: ti = tid&31 owns 4 i (2 packed f32x2 pairs), tj = tid>>5 owns 8 j
// (warp-uniform -> B-fragment LDS is broadcast). 16 FFMA2 per c-step.
// Scan: qi = tid&127, qq = tid>>7; each thread scans 32 j of the previous tile,
// maintaining top-K as packed u64 keys (ord(dist)<<32 | idx) in shared.
// Final: tid<128 merges the 4 quarter lists (u64 order = dist then idx).
__global__ void __launch_bounds__(NT) k_knn5(const float* __restrict__ x) {
    extern __shared__ float sm[];
    u64*   keys = (u64*)sm;                        // [Kc][NT]
    float* As   = sm + (Kc * NT * 2);              // [Cc][APAD]
    float* Bs   = As + Cc * APAD;                  // [Cc][APAD]
    float* Ds   = Bs + Cc * APAD;                  // [TJ][APAD]
    float* sxxi = Ds + TJ * APAD;                  // [128]
    float* sxxj = sxxi + 128;                      // [128]

    const int tid = threadIdx.x;
    const int b   = blockIdx.y;
    const int i0  = blockIdx.x * TI;
    const float* xb = x + (size_t)b * Cc * Nc;

    const int ti = tid & 31;      // i-group (4 queries)
    const int tj = tid >> 5;      // j-group (8 candidates), warp-uniform
    const int qi = tid & 127;     // scan query
    const int qq = tid >> 7;      // scan quarter

    // load A tile: As[c][ii] = x[b][c][i0+ii]
    {
        int col = (tid & 31) * 4;
        int cb  = tid >> 5;
#pragma unroll
        for (int cc = 0; cc < 4; ++cc) {
            int c = cb + cc * 16;
            float4 v = *(const float4*)&xb[(size_t)c * Nc + i0 + col];
            *(float4*)&As[c * APAD + col] = v;
        }
    }
    if (tid < 128) sxxi[tid] = g_xx[b * Nc + i0 + tid];
#pragma unroll
    for (int kk = 0; kk < Kc; ++kk) keys[kk * NT + tid] = KEY_MAX;
    __syncthreads();

    // packed query norms for this thread's 2 i-pairs
    u64 xq[2];
    {
        ulonglong2 t0 = *(const ulonglong2*)&sxxi[ti * 4];
        xq[0] = t0.x; xq[1] = t0.y;
    }
    const u64 neg2 = dup2(-2.f);
    u64 worst = KEY_MAX;

    for (int t = 0; t < Nc / TJ; ++t) {
        const int j0 = t * TJ;

        // load B tile global -> shared (overlaps with scan below)
        {
            int col = (tid & 31) * 4;
            int cb  = tid >> 5;
#pragma unroll
            for (int cc = 0; cc < 4; ++cc) {
                int c = cb + cc * 16;
                float4 v = *(const float4*)&xb[(size_t)c * Nc + j0 + col];
                *(float4*)&Bs[c * APAD + col] = v;
            }
        }
        if (tid < 128) sxxj[tid] = g_xx[b * Nc + j0 + tid];

        // scan previous tile's distances
        if (t > 0) {
            const int jp0 = j0 - TJ;
#pragma unroll 1
            for (int jj = 0; jj < 32; ++jj) {
                int jl = qq * 32 + jj;
                float d = Ds[jl * APAD + qi];
                u64 key = ((u64)ordf(d) << 32) | (u32)(jp0 + jl);
                if (key < worst) {
                    int p = Kc - 1;
                    while (p > 0) {
                        u64 v = keys[(p - 1) * NT + tid];
                        if (v < key) break;
                        keys[p * NT + tid] = v;
                        --p;
                    }
                    keys[p * NT + tid] = key;
                    worst = keys[(Kc - 1) * NT + tid];
                }
            }
        }
        __syncthreads();   // B ready; Ds free for rewrite

        // ---- 4x8 f32x2 GEMM over c ----
        u64 acc[2][8];
#pragma unroll
        for (int ip = 0; ip < 2; ++ip)
#pragma unroll
            for (int j = 0; j < 8; ++j) acc[ip][j] = 0ULL;

#pragma unroll 4
        for (int c = 0; c < Cc; ++c) {
            ulonglong2 a01 = *(const ulonglong2*)&As[c * APAD + ti * 4];
            u64 ap0 = a01.x, ap1 = a01.y;
            float4 b0 = *(const float4*)&Bs[c * APAD + tj * 8];
            float4 b1 = *(const float4*)&Bs[c * APAD + tj * 8 + 4];
            u64 bd0 = dup2(b0.x), bd1 = dup2(b0.y), bd2 = dup2(b0.z), bd3 = dup2(b0.w);
            u64 bd4 = dup2(b1.x), bd5 = dup2(b1.y), bd6 = dup2(b1.z), bd7 = dup2(b1.w);
            ffma2(acc[0][0], ap0, bd0); ffma2(acc[1][0], ap1, bd0);
            ffma2(acc[0][1], ap0, bd1); ffma2(acc[1][1], ap1, bd1);
            ffma2(acc[0][2], ap0, bd2); ffma2(acc[1][2], ap1, bd2);
            ffma2(acc[0][3], ap0, bd3); ffma2(acc[1][3], ap1, bd3);
            ffma2(acc[0][4], ap0, bd4); ffma2(acc[1][4], ap1, bd4);
            ffma2(acc[0][5], ap0, bd5); ffma2(acc[1][5], ap1, bd5);
            ffma2(acc[0][6], ap0, bd6); ffma2(acc[1][6], ap1, bd6);
            ffma2(acc[0][7], ap0, bd7); ffma2(acc[1][7], ap1, bd7);
        }

        // epilogue: d = xxi + xxj - 2*inner (packed), store Ds[j][i]
#pragma unroll
        for (int j = 0; j < 8; ++j) {
            u64 xjd = dup2(sxxj[tj * 8 + j]);
            int row = (tj * 8 + j) * APAD + ti * 4;
#pragma unroll
            for (int ip = 0; ip < 2; ++ip) {
                u64 pre = add2(xq[ip], xjd);
                u64 d2  = fma2o(acc[ip][j], neg2, pre);
                *(u64*)&Ds[row + ip * 2] = d2;
            }
        }
        __syncthreads();   // Ds visible; Bs consumed
    }

    // scan last tile
    {
        const int jp0 = Nc - TJ;
#pragma unroll 1
        for (int jj = 0; jj < 32; ++jj) {
            int jl = qq * 32 + jj;
            float d = Ds[jl * APAD + qi];
            u64 key = ((u64)ordf(d) << 32) | (u32)(jp0 + jl);
            if (key < worst) {
                int p = Kc - 1;
                while (p > 0) {
                    u64 v = keys[(p - 1) * NT + tid];
                    if (v < key) break;
                    keys[p * NT + tid] = v;
                    --p;
                }
                keys[p * NT + tid] = key;
                worst = keys[(Kc - 1) * NT + tid];
            }
        }
    }
    __syncthreads();

    // merge the 4 quarter lists per query (u64 order = dist, then idx)
    if (tid < 128) {
        u64 tk[Kc];
#pragma unroll
        for (int kk = 0; kk < Kc; ++kk) tk[kk] = KEY_MAX;
        for (int s = 0; s < 4; ++s) {
#pragma unroll 1
            for (int kk = 0; kk < Kc; ++kk) {
                u64 key = keys[kk * NT + s * 128 + tid];
                if (!(key < tk[Kc - 1])) break;   // sorted ascending source list
                int p = Kc - 1;
                while (p > 0 && tk[p - 1] > key) {
                    tk[p] = tk[p - 1];
                    --p;
                }
                tk[p] = key;
            }
        }
        int* op = &g_idx[((size_t)(b * Nc + i0 + tid)) * Kc];
#pragma unroll
        for (int kk = 0; kk < Kc; ++kk) op[kk] = (int)(u32)(tk[kk] & 0xFFFFFFFFull);
    }
}

// -------------------- kernel: gather + max/min + BN stats --------------------
__global__ void __launch_bounds__(256) k_edge() {
    int o  = threadIdx.x & 63;
    int gg = threadIdx.x >> 6;
    float s1 = 0.f, s2v = 0.f;

    for (int row = blockIdx.x * 4 + gg; row < Bc * Nc; row += gridDim.x * 4) {
        int b  = row >> 12;
        int nb = b << 12;
        float qv = g_Q[(size_t)row * Oc + o];
        const int* ip = &g_idx[(size_t)row * Kc];
        float mx = -FLT_BIG, mn = FLT_BIG;
#pragma unroll
        for (int kk = 0; kk < Kc; ++kk) {
            int j = __ldg(&ip[kk]);
            float h = g_P[(size_t)(nb + j) * Oc + o] + qv;
            mx = fmaxf(mx, h);
            mn = fminf(mn, h);
            s1 += h;
            s2v = fmaf(h, h, s2v);
        }
        g_mx[(size_t)row * Oc + o] = mx;
        g_mn[(size_t)row * Oc + o] = mn;
    }

    __shared__ float sa[4][64], sb[4][64];
    sa[gg][o] = s1;
    sb[gg][o] = s2v;
    __syncthreads();
    if (gg == 0) {
        float t1 = sa[0][o] + sa[1][o] + sa[2][o] + sa[3][o];
        float t2 = sb[0][o] + sb[1][o] + sb[2][o] + sb[3][o];
        atomicAdd(&g_sum[o], (double)t1);
        atomicAdd(&g_sumsq[o], (double)t2);
    }
}

// -------------------- kernel: finalize BN affine --------------------
__global__ void k_fin(const float* __restrict__ gamma, const float* __restrict__ beta) {
    int o = threadIdx.x;
    const double cnt = (double)Bc * Nc * Kc;
    double mean = g_sum[o] / cnt;
    double var  = g_sumsq[o] / cnt - mean * mean;
    float a = gamma[o] * rsqrtf((float)var + BN_EPS);
    g_scale[o] = a;
    g_shift[o] = beta[o] - (float)mean * a;
}

// -------------------- kernel: apply affine + leaky + transpose to [B,O,N] --------------------
__global__ void __launch_bounds__(256) k_out(float* __restrict__ out) {
    int b  = blockIdx.y;
    int n0 = blockIdx.x * 64;
    __shared__ float sh[64][65];

    for (int t = threadIdx.x; t < 4096; t += 256) {
        int o  = t & 63;
        int nn = t >> 6;
        int row = b * Nc + n0 + nn;
        float a = g_scale[o];
        float m = (a >= 0.f) ? g_mx[(size_t)row * Oc + o] : g_mn[(size_t)row * Oc + o];
        float v = fmaf(a, m, g_shift[o]);
        v = (v >= 0.f) ? v : NEG_SLOPE * v;
        sh[o][nn] = v;
    }
    __syncthreads();
    for (int t = threadIdx.x; t < 4096; t += 256) {
        int nn = t & 63;
        int o  = t >> 6;
        out[((size_t)(b * Oc + o)) * Nc + n0 + nn] = sh[o][nn];
    }
}

// -------------------- launch --------------------
extern "C" void kernel_launch(void* const* d_in, const int* in_sizes, int n_in,
                              void* d_out, int out_size) {
    const float* x     = (const float*)d_in[0];   // [B, C, N]
    const float* W     = (const float*)d_in[1];   // [O, 2C]
    const float* gamma = (const float*)d_in[2];   // [O]
    const float* beta  = (const float*)d_in[3];   // [O]
    float* out = (float*)d_out;                   // [B, O, N]

    // keys [Kc][NT] u64 + As/Bs [Cc][APAD] + Ds [TJ][APAD] + sxx
    constexpr size_t KNN_SMEM =
        (size_t)Kc * NT * 8 +
        (size_t)(2 * Cc * APAD + TJ * APAD + 256) * 4;

    static bool attr_set = false;
    if (!attr_set) {
        cudaFuncSetAttribute(k_knn5, cudaFuncAttributeMaxDynamicSharedMemorySize,
                             (int)KNN_SMEM);
        attr_set = true;
    }

    k_xx<<<(Bc * Nc) / 256, 256>>>(x);
    k_prep<<<16, 256>>>(W);
    k_pq<<<dim3(Nc / 32, Bc), 256>>>(x);
    k_knn5<<<dim3(Nc / TI, Bc), NT, KNN_SMEM>>>(x);
    k_edge<<<512, 256>>>();
    k_fin<<<1, Oc>>>(gamma, beta);
    k_out<<<dim3(Nc / 64, Bc), 256>>>(out);
}